// round 16
// baseline (speedup 1.0000x reference)
#include <cuda_runtime.h>
#include <cuda_fp16.h>
#include <cstdint>

// Problem constants
#define BB 2
#define TT 2048
#define CC 1024
#define HH 16
#define GG 4
#define HD 64
#define KV 256
#define ROWS (BB * TT)  // 4096

// Q scale with folded log2(e) for exp2-based softmax
#define QSCALE (0.125f * 1.44269504088896f)

// Scratch (allocation-free rule: __device__ globals)
__device__ __half g_Xh[ROWS * CC];    // fp16 x
__device__ __half g_Qh[ROWS * CC];    // fp16 Q (pre-scaled by QSCALE)
__device__ __half g_Kh[ROWS * KV];    // fp16 K, row-major
__device__ __half g_Vt[ROWS * KV];    // fp16 V TRANSPOSED: [b][g][d=64][t=2048]
__device__ __half g_Oh[ROWS * CC];    // fp16 attention output
__device__ __half g_Wqh[CC * CC];     // fp16 weights, k-pair-interleaved
__device__ __half g_Wkh[CC * KV];
__device__ __half g_Wvh[CC * KV];
__device__ __half g_Wph[CC * CC];

// ---------------------------------------------------------------------------
// helpers
// ---------------------------------------------------------------------------
__device__ __forceinline__ uint32_t smem_u32(const void* p) {
    uint32_t a;
    asm("{ .reg .u64 t; cvta.to.shared.u64 t, %1; cvt.u32.u64 %0, t; }"
        : "=r"(a) : "l"(p));
    return a;
}

__device__ __forceinline__ void cp_async16(uint32_t saddr, const void* g) {
    asm volatile("cp.async.cg.shared.global [%0], [%1], 16;"
                 :: "r"(saddr), "l"(g) : "memory");
}
#define CP_COMMIT() asm volatile("cp.async.commit_group;" ::: "memory")
#define CP_WAIT(n)  asm volatile("cp.async.wait_group %0;" :: "n"(n) : "memory")

// fp16 m16n8k16, fp32 accum
__device__ __forceinline__ void mma_f16(float* d, const unsigned* a,
                                        unsigned b0, unsigned b1) {
    asm volatile(
        "mma.sync.aligned.m16n8k16.row.col.f32.f16.f16.f32 "
        "{%0,%1,%2,%3}, {%4,%5,%6,%7}, {%8,%9}, {%0,%1,%2,%3};"
        : "+f"(d[0]), "+f"(d[1]), "+f"(d[2]), "+f"(d[3])
        : "r"(a[0]), "r"(a[1]), "r"(a[2]), "r"(a[3]),
          "r"(b0), "r"(b1));
}

// ldmatrix x4: 4 8x8 b16 tiles, lane r supplies row r%8 of tile r/8
__device__ __forceinline__ void ldsm_x4(unsigned& r0, unsigned& r1,
                                        unsigned& r2, unsigned& r3,
                                        uint32_t addr) {
    asm volatile("ldmatrix.sync.aligned.m8n8.x4.shared.b16 {%0,%1,%2,%3}, [%4];"
                 : "=r"(r0), "=r"(r1), "=r"(r2), "=r"(r3) : "r"(addr));
}

// single-instruction MUFU exp2
__device__ __forceinline__ float ex2(float x) {
    float y;
    asm("ex2.approx.ftz.f32 %0, %1;" : "=f"(y) : "f"(x));
    return y;
}

// pack two floats into one fp16x2 register (FULL 32 bits)
__device__ __forceinline__ unsigned pack_half2(float a, float b) {
    __half2 h = __floats2half2_rn(a, b);
    return *reinterpret_cast<unsigned*>(&h);
}

// ---------------------------------------------------------------------------
// Prepass 1: x -> fp16
// ---------------------------------------------------------------------------
__global__ void __launch_bounds__(256) cvt_x16_kernel(
    const float* __restrict__ in, __half* __restrict__ out, int n4)
{
    int i = blockIdx.x * 256 + threadIdx.x;
    if (i < n4) {
        float4 v = ((const float4*)in)[i];
        __half2 h0 = __floats2half2_rn(v.x, v.y);
        __half2 h1 = __floats2half2_rn(v.z, v.w);
        *(__half2*)&out[i * 4]     = h0;
        *(__half2*)&out[i * 4 + 2] = h1;
    }
}

// Prepass 2: all 4 weights -> fp16, k-pair-interleaved:
//   out[(k>>1)*2N + 2n + (k&1)] = in[k*N + n]
__global__ void __launch_bounds__(256) cvt_weights_kernel(
    const float* __restrict__ Wq, __half* __restrict__ Wqh,
    const float* __restrict__ Wk, __half* __restrict__ Wkh,
    const float* __restrict__ Wv, __half* __restrict__ Wvh,
    const float* __restrict__ Wp, __half* __restrict__ Wph)
{
    const int m = blockIdx.y;
    const float* in; __half* out; int N;
    if (m == 0)      { in = Wq; out = Wqh; N = CC; }
    else if (m == 1) { in = Wk; out = Wkh; N = KV; }
    else if (m == 2) { in = Wv; out = Wvh; N = KV; }
    else             { in = Wp; out = Wph; N = CC; }
    const int total = (CC / 2) * N;
    int idx = blockIdx.x * 256 + threadIdx.x;
    if (idx < total) {
        int kp = idx / N, n = idx % N;
        float a = in[(size_t)(2 * kp) * N + n];
        float b = in[(size_t)(2 * kp + 1) * N + n];
        *(__half2*)&out[(size_t)kp * 2 * N + 2 * n] = __floats2half2_rn(a, b);
    }
}

// ---------------------------------------------------------------------------
// FP16 mma.sync GEMM (unchanged): 128x128 tile, BK=32, 128 thr.
// Epilogue mode 3 now writes V TRANSPOSED: Vt[(b*G+g)*64 + d][t].
// ---------------------------------------------------------------------------
#define A_ST 40
#define B_ST 272
#define STAGE_HALVES (128 * A_ST + 16 * B_ST)     // 9472
#define GEMM_SMEM_BYTES (2 * STAGE_HALVES * 2)    // 37888

__device__ __forceinline__ void gemm_issue16(
    __half* smem_h, int st, const __half* __restrict__ Ag,
    const __half* __restrict__ Bg, int Kdim, int N2, int k0, int tid)
{
    __half* dA = smem_h + st * STAGE_HALVES;
    __half* dB = dA + 128 * A_ST;
#pragma unroll
    for (int t = 0; t < 4; t++) {
        int ch = tid + (t << 7);
        int r = ch >> 2;
        int c8 = (ch & 3) << 3;
        cp_async16(smem_u32(dA + r * A_ST + c8),
                   Ag + (size_t)r * Kdim + k0 + c8);
    }
#pragma unroll
    for (int t = 0; t < 4; t++) {
        int ch = tid + (t << 7);
        int kp = ch >> 5;
        int c8 = (ch & 31) << 3;
        cp_async16(smem_u32(dB + kp * B_ST + c8),
                   Bg + (size_t)((k0 >> 1) + kp) * N2 + c8);
    }
}

__device__ __forceinline__ void gemm_body16(
    const __half* __restrict__ A, const __half* __restrict__ Bw,
    const float* __restrict__ bias, void* __restrict__ Cd,
    int N, int Kdim, int bx, int by, __half* smem_h, int mode)
{
    const int tid = threadIdx.x;
    const int lane = tid & 31;
    const int warp = tid >> 5;
    const int gid = lane >> 2;
    const int tig = lane & 3;
    const int wm = (warp & 1) << 6;
    const int wn = (warp >> 1) << 6;
    const int bm = by << 7;
    const int bn = bx << 7;

    const __half* Ag = A + (size_t)bm * Kdim;
    const __half* Bg = Bw + bn * 2;
    const int N2 = N * 2;
    const int ntiles = Kdim >> 5;

    float acc[4][8][4];
#pragma unroll
    for (int mi = 0; mi < 4; mi++)
#pragma unroll
        for (int ni = 0; ni < 8; ni++)
#pragma unroll
            for (int c = 0; c < 4; c++) acc[mi][ni][c] = 0.0f;

    gemm_issue16(smem_h, 0, Ag, Bg, Kdim, N2, 0, tid);
    CP_COMMIT();

    for (int kt = 0; kt < ntiles; kt++) {
        if (kt + 1 < ntiles) {
            gemm_issue16(smem_h, (kt + 1) & 1, Ag, Bg, Kdim, N2, (kt + 1) << 5, tid);
            CP_COMMIT();
            CP_WAIT(1);
        } else {
            CP_WAIT(0);
        }
        __syncthreads();

        const __half* As_ = smem_h + (kt & 1) * STAGE_HALVES;
        const __half* Bs_ = As_ + 128 * A_ST;
#pragma unroll
        for (int jj = 0; jj < 2; jj++) {
            unsigned a[4][4];
#pragma unroll
            for (int mi = 0; mi < 4; mi++) {
                int base = (wm + (mi << 4) + gid) * A_ST + (jj << 4) + (tig << 1);
                a[mi][0] = *(const unsigned*)(As_ + base);
                a[mi][1] = *(const unsigned*)(As_ + base + 8 * A_ST);
                a[mi][2] = *(const unsigned*)(As_ + base + 8);
                a[mi][3] = *(const unsigned*)(As_ + base + 8 * A_ST + 8);
            }
#pragma unroll
            for (int ni = 0; ni < 8; ni++) {
                int n = wn + (ni << 3) + gid;
                int kp = (jj << 3) + tig;
                unsigned b0 = *(const unsigned*)(Bs_ + kp * B_ST + n * 2);
                unsigned b1 = *(const unsigned*)(Bs_ + (kp + 4) * B_ST + n * 2);
#pragma unroll
                for (int mi = 0; mi < 4; mi++)
                    mma_f16(acc[mi][ni], a[mi], b0, b1);
            }
        }
        __syncthreads();
    }

#pragma unroll
    for (int mi = 0; mi < 4; mi++) {
        int r0 = bm + wm + (mi << 4) + gid;
#pragma unroll
        for (int ni = 0; ni < 8; ni++) {
            int c = bn + wn + (ni << 3) + (tig << 1);
            float2 bb = *(const float2*)&bias[c];
            float o00 = acc[mi][ni][0] + bb.x;
            float o01 = acc[mi][ni][1] + bb.y;
            float o10 = acc[mi][ni][2] + bb.x;
            float o11 = acc[mi][ni][3] + bb.y;
            if (mode == 0) {
                float* C = (float*)Cd;
                *(float2*)&C[(size_t)r0 * N + c] = make_float2(o00, o01);
                *(float2*)&C[(size_t)(r0 + 8) * N + c] = make_float2(o10, o11);
            } else if (mode == 1) {
                __half* C = (__half*)Cd;
                *(__half2*)&C[(size_t)r0 * N + c] =
                    __floats2half2_rn(o00 * QSCALE, o01 * QSCALE);
                *(__half2*)&C[(size_t)(r0 + 8) * N + c] =
                    __floats2half2_rn(o10 * QSCALE, o11 * QSCALE);
            } else if (mode == 2) {
                __half* C = (__half*)Cd;
                *(__half2*)&C[(size_t)r0 * N + c] = __floats2half2_rn(o00, o01);
                *(__half2*)&C[(size_t)(r0 + 8) * N + c] = __floats2half2_rn(o10, o11);
            } else {
                // V transposed: Vt[((b*G+g)*64 + d) * TT + t]
                __half* C = (__half*)Cd;
                int gg = c >> 6, d = c & 63;
                int b0_ = r0 >> 11, t0 = r0 & 2047;
                int b1_ = (r0 + 8) >> 11, t1 = (r0 + 8) & 2047;
                size_t base0 = (size_t)(b0_ * GG + gg) * HD;
                size_t base1 = (size_t)(b1_ * GG + gg) * HD;
                C[(base0 + d) * TT + t0]     = __float2half_rn(o00);
                C[(base0 + d + 1) * TT + t0] = __float2half_rn(o01);
                C[(base1 + d) * TT + t1]     = __float2half_rn(o10);
                C[(base1 + d + 1) * TT + t1] = __float2half_rn(o11);
            }
        }
    }
}

__global__ void __launch_bounds__(128, 3) gemm_qkv_kernel(
    const __half* __restrict__ Xh,
    const __half* __restrict__ Wq, const float* __restrict__ bq, __half* __restrict__ Qh,
    const __half* __restrict__ Wk, const float* __restrict__ bk, __half* __restrict__ Kh,
    const __half* __restrict__ Wv, const float* __restrict__ bv, __half* __restrict__ Vt)
{
    extern __shared__ __align__(16) __half smem_h[];
    const int bx = blockIdx.x;
    const __half* Bw; const float* bias; void* Cd; int N, bxx, mode;
    if (bx < 8)       { Bw = Wq; bias = bq; Cd = Qh; N = CC; bxx = bx;      mode = 1; }
    else if (bx < 10) { Bw = Wk; bias = bk; Cd = Kh; N = KV; bxx = bx - 8;  mode = 2; }
    else              { Bw = Wv; bias = bv; Cd = Vt; N = KV; bxx = bx - 10; mode = 3; }
    gemm_body16(Xh, Bw, bias, Cd, N, CC, bxx, blockIdx.y, smem_h, mode);
}

__global__ void __launch_bounds__(128, 3) gemm_p_kernel(
    const __half* __restrict__ A, const __half* __restrict__ Wp,
    const float* __restrict__ bp, float* __restrict__ out)
{
    extern __shared__ __align__(16) __half smem_h[];
    gemm_body16(A, Wp, bp, out, CC, CC, blockIdx.x, blockIdx.y, smem_h, 0);
}

// ---------------------------------------------------------------------------
// Causal GQA flash attention v4: fp16 m16n8k16, fp32 softmax/accum.
// Block = 128 q-rows x head. 8 warps; warp owns 16 q-rows. k-tile = 64.
// K AND V fragments via ldmatrix.x4 (4x fewer operand-load instructions).
// V global layout transposed [b][g][d][t]; smem V stage [64 d][72] halves.
// Register-resident P, conditional rescale, MUFU exp2.
// Smem (halves): K st @ st*4608 [64][72]; V st @ 9216+st*4608 [64][72].
// Q staging overlays K region during prologue. Total 36,864 B (static).
// ---------------------------------------------------------------------------
__global__ void __launch_bounds__(256, 2) attn_f16_kernel(
    const __half* __restrict__ Qh, const __half* __restrict__ Kh,
    const __half* __restrict__ Vt, __half* __restrict__ O)
{
    __shared__ __align__(16) __half sbh[18432];  // 36,864 B

    const int tid = threadIdx.x;
    const int lane = tid & 31;
    const int w = tid >> 5;
    const int gid = lane >> 2;
    const int tig = lane & 3;
    const int qt = gridDim.x - 1 - blockIdx.x;  // heavy tiles first
    const int q0 = qt << 7;
    const int h = blockIdx.y;
    const int b = blockIdx.z;
    const int g = h >> 2;

    const __half* Qg = Qh + (size_t)(b * TT + q0) * CC + h * HD;
    const __half* Kg = Kh + (size_t)(b * TT) * KV + g * HD;
    const __half* Vg = Vt + (size_t)(b * GG + g) * HD * TT;

    // Prologue: stage Q fp16 into [128][72] (overlays K buffers)
#pragma unroll
    for (int t = 0; t < 4; t++) {
        int ch = tid + (t << 8);
        int r = ch >> 3;
        int c8 = (ch & 7) << 3;
        cp_async16(smem_u32(sbh + r * 72 + c8), Qg + (size_t)r * CC + c8);
    }
    CP_COMMIT();
    CP_WAIT(0);
    __syncthreads();

    const int rl = (w << 4) + gid;
    unsigned qa[4][4];
#pragma unroll
    for (int jj = 0; jj < 4; jj++) {
        int base = rl * 72 + (jj << 4) + (tig << 1);
        qa[jj][0] = *(const unsigned*)(sbh + base);
        qa[jj][1] = *(const unsigned*)(sbh + base + 8 * 72);
        qa[jj][2] = *(const unsigned*)(sbh + base + 8);
        qa[jj][3] = *(const unsigned*)(sbh + base + 8 * 72 + 8);
    }
    __syncthreads();  // Q staging dead -> K/V buffers live

    float m_lo = -1e30f, m_hi = -1e30f, l_lo = 0.0f, l_hi = 0.0f;
    float acc[8][4];
#pragma unroll
    for (int nd = 0; nd < 8; nd++)
#pragma unroll
        for (int c = 0; c < 4; c++) acc[nd][c] = 0.0f;

    const int row_lo = q0 + rl;
    const int row_hi = row_lo + 8;
    const int ktiles = (q0 >> 6) + 2;   // 64-key tiles; diagonal span 128

    // ldmatrix lane offset: tile row (lane&7) + tile-pair select (lane>>3):
    //   bit0 -> +8 cols (k-halves), bit1 -> +8 rows
    const int mrow = lane & 7;
    const int msel = lane >> 3;
    const int laneoff = (((msel >> 1) << 3) + mrow) * 72 + ((msel & 1) << 3);
    const uint32_t sb32 = smem_u32(sbh);

    // cp.async per 64-key tile: K 512 chunks + V 512 chunks -> 2+2 per thread
#define ATTN_ISSUE(kt_) do {                                                \
    int _st = (kt_) & 1;                                                    \
    int _k0 = (kt_) << 6;                                                   \
    _Pragma("unroll")                                                       \
    for (int _t = 0; _t < 2; _t++) {                                        \
        int _ch = tid + (_t << 8);                                          \
        int _r = _ch >> 3, _c8 = (_ch & 7) << 3;                            \
        cp_async16(smem_u32(sbh + _st * 4608 + _r * 72 + _c8),              \
                   Kg + (size_t)(_k0 + _r) * KV + _c8);                     \
        cp_async16(smem_u32(sbh + 9216 + _st * 4608 + _r * 72 + _c8),       \
                   Vg + (size_t)_r * TT + _k0 + _c8);                       \
    }                                                                       \
} while (0)

    ATTN_ISSUE(0);
    CP_COMMIT();

    for (int kt = 0; kt < ktiles; kt++) {
        if (kt + 1 < ktiles) {
            ATTN_ISSUE(kt + 1);
            CP_COMMIT();
            CP_WAIT(1);
        } else {
            CP_WAIT(0);
        }
        __syncthreads();

        const int st = kt & 1;
        const uint32_t kbase = sb32 + ((st * 4608 + laneoff) << 1);
        const uint32_t vbase = sb32 + ((9216 + st * 4608 + laneoff) << 1);
        const int k0 = kt << 6;

        // S = Q @ K^T : 4 d16-steps x 4 key16-pairs, ldmatrix.x4 per pair
        float s[8][4];
#pragma unroll
        for (int ni = 0; ni < 8; ni++)
#pragma unroll
            for (int c = 0; c < 4; c++) s[ni][c] = 0.0f;

#pragma unroll
        for (int jj = 0; jj < 4; jj++) {
#pragma unroll
            for (int nip = 0; nip < 4; nip++) {
                unsigned b00, b01, b10, b11;
                ldsm_x4(b00, b01, b10, b11,
                        kbase + ((nip * 1152 + jj * 16) << 1));
                mma_f16(s[2 * nip],     qa[jj], b00, b01);
                mma_f16(s[2 * nip + 1], qa[jj], b10, b11);
            }
        }

        // causal mask (only diagonal-overlapping tiles)
        if (k0 + 63 > q0) {
#pragma unroll
            for (int ni = 0; ni < 8; ni++) {
                int cg = k0 + (ni << 3) + (tig << 1);
                if (cg > row_lo)     s[ni][0] = -1e30f;
                if (cg + 1 > row_lo) s[ni][1] = -1e30f;
                if (cg > row_hi)     s[ni][2] = -1e30f;
                if (cg + 1 > row_hi) s[ni][3] = -1e30f;
            }
        }

        // online softmax (base-2; scale folded into Q)
        float mx_lo = -1e30f, mx_hi = -1e30f;
#pragma unroll
        for (int ni = 0; ni < 8; ni++) {
            mx_lo = fmaxf(mx_lo, fmaxf(s[ni][0], s[ni][1]));
            mx_hi = fmaxf(mx_hi, fmaxf(s[ni][2], s[ni][3]));
        }
        mx_lo = fmaxf(mx_lo, __shfl_xor_sync(0xffffffffu, mx_lo, 1));
        mx_lo = fmaxf(mx_lo, __shfl_xor_sync(0xffffffffu, mx_lo, 2));
        mx_hi = fmaxf(mx_hi, __shfl_xor_sync(0xffffffffu, mx_hi, 1));
        mx_hi = fmaxf(mx_hi, __shfl_xor_sync(0xffffffffu, mx_hi, 2));

        float mn_lo = fmaxf(m_lo, mx_lo);
        float mn_hi = fmaxf(m_hi, mx_hi);
        bool rescale = (mn_lo > m_lo) || (mn_hi > m_hi);
        float alpha_lo = ex2(m_lo - mn_lo);
        float alpha_hi = ex2(m_hi - mn_hi);
        m_lo = mn_lo; m_hi = mn_hi;

        float sum_lo = 0.0f, sum_hi = 0.0f;
#pragma unroll
        for (int ni = 0; ni < 8; ni++) {
            s[ni][0] = ex2(s[ni][0] - mn_lo);
            s[ni][1] = ex2(s[ni][1] - mn_lo);
            s[ni][2] = ex2(s[ni][2] - mn_hi);
            s[ni][3] = ex2(s[ni][3] - mn_hi);
            sum_lo += s[ni][0] + s[ni][1];
            sum_hi += s[ni][2] + s[ni][3];
        }
        sum_lo += __shfl_xor_sync(0xffffffffu, sum_lo, 1);
        sum_lo += __shfl_xor_sync(0xffffffffu, sum_lo, 2);
        sum_hi += __shfl_xor_sync(0xffffffffu, sum_hi, 1);
        sum_hi += __shfl_xor_sync(0xffffffffu, sum_hi, 2);
        l_lo = l_lo * alpha_lo + sum_lo;
        l_hi = l_hi * alpha_hi + sum_hi;

        if (rescale) {
#pragma unroll
            for (int nd = 0; nd < 8; nd++) {
                acc[nd][0] *= alpha_lo; acc[nd][1] *= alpha_lo;
                acc[nd][2] *= alpha_hi; acc[nd][3] *= alpha_hi;
            }
        }

        // P: C-fragment of S == A-fragment for PV; pack in registers.
        unsigned pa[4][4];
#pragma unroll
        for (int jj2 = 0; jj2 < 4; jj2++) {
            pa[jj2][0] = pack_half2(s[2*jj2][0],   s[2*jj2][1]);
            pa[jj2][1] = pack_half2(s[2*jj2][2],   s[2*jj2][3]);
            pa[jj2][2] = pack_half2(s[2*jj2+1][0], s[2*jj2+1][1]);
            pa[jj2][3] = pack_half2(s[2*jj2+1][2], s[2*jj2+1][3]);
        }

        // O += P @ V : 4 key16-steps x 4 d16-pairs, ldmatrix.x4 per pair
#pragma unroll
        for (int jj2 = 0; jj2 < 4; jj2++) {
#pragma unroll
            for (int ndp = 0; ndp < 4; ndp++) {
                unsigned v00, v01, v10, v11;
                ldsm_x4(v00, v01, v10, v11,
                        vbase + ((ndp * 1152 + jj2 * 16) << 1));
                mma_f16(acc[2 * ndp],     pa[jj2], v00, v01);
                mma_f16(acc[2 * ndp + 1], pa[jj2], v10, v11);
            }
        }
        __syncthreads();
    }

    // epilogue: normalize, emit fp16 O (feeds fp16 final projection)
    float inv_lo = 1.0f / l_lo;
    float inv_hi = 1.0f / l_hi;
    __half* Og = O + (size_t)(b * TT + q0 + rl) * CC + h * HD;
#pragma unroll
    for (int nd = 0; nd < 8; nd++) {
        int c = (nd << 3) + (tig << 1);
        *(__half2*)&Og[c] =
            __floats2half2_rn(acc[nd][0] * inv_lo, acc[nd][1] * inv_lo);
        *(__half2*)&Og[(size_t)8 * CC + c] =
            __floats2half2_rn(acc[nd][2] * inv_hi, acc[nd][3] * inv_hi);
    }
#undef ATTN_ISSUE
}

// ---------------------------------------------------------------------------
extern "C" void kernel_launch(void* const* d_in, const int* in_sizes, int n_in,
                              void* d_out, int out_size)
{
    (void)in_sizes; (void)n_in; (void)out_size;
    const float* x  = (const float*)d_in[0];
    const float* Wq = (const float*)d_in[1];
    const float* bq = (const float*)d_in[2];
    const float* Wk = (const float*)d_in[3];
    const float* bk = (const float*)d_in[4];
    const float* Wv = (const float*)d_in[5];
    const float* bv = (const float*)d_in[6];
    const float* Wp = (const float*)d_in[7];
    const float* bp = (const float*)d_in[8];
    float* out = (float*)d_out;

    __half *Xh, *Qh, *Kh, *Vtp, *Oh, *Wqh, *Wkh, *Wvh, *Wph;
    cudaGetSymbolAddress((void**)&Xh, g_Xh);
    cudaGetSymbolAddress((void**)&Qh, g_Qh);
    cudaGetSymbolAddress((void**)&Kh, g_Kh);
    cudaGetSymbolAddress((void**)&Vtp, g_Vt);
    cudaGetSymbolAddress((void**)&Oh, g_Oh);
    cudaGetSymbolAddress((void**)&Wqh, g_Wqh);
    cudaGetSymbolAddress((void**)&Wkh, g_Wkh);
    cudaGetSymbolAddress((void**)&Wvh, g_Wvh);
    cudaGetSymbolAddress((void**)&Wph, g_Wph);

    cudaFuncSetAttribute(gemm_qkv_kernel,
                         cudaFuncAttributeMaxDynamicSharedMemorySize, GEMM_SMEM_BYTES);
    cudaFuncSetAttribute(gemm_p_kernel,
                         cudaFuncAttributeMaxDynamicSharedMemorySize, GEMM_SMEM_BYTES);

    // Prepass: x -> fp16; weights -> fp16 k-pair-interleaved (2 launches)
    cvt_x16_kernel<<<(ROWS * CC / 4 + 255) / 256, 256>>>(x, Xh, ROWS * CC / 4);
    cvt_weights_kernel<<<dim3((CC / 2 * CC + 255) / 256, 4), 256>>>(
        Wq, Wqh, Wk, Wkh, Wv, Wvh, Wp, Wph);

    // Fused Q/K/V projections (V emitted transposed)
    gemm_qkv_kernel<<<dim3(12, ROWS / 128), 128, GEMM_SMEM_BYTES>>>(
        Xh, Wqh, bq, Qh, Wkh, bk, Kh, Wvh, bv, Vtp);

    // Causal GQA attention (ldmatrix operand loads, register-resident P)
    attn_f16_kernel<<<dim3(TT / 128, HH, BB), 256>>>(Qh, Kh, Vtp, Oh);

    // Output projection (fp16 in, fp32 out)
    gemm_p_kernel<<<dim3(CC / 128, ROWS / 128), 128, GEMM_SMEM_BYTES>>>(
        Oh, Wph, bp, out);
}

// round 17
// speedup vs baseline: 1.0221x; 1.0221x over previous
#include <cuda_runtime.h>
#include <cuda_fp16.h>
#include <cstdint>

// Problem constants
#define BB 2
#define TT 2048
#define CC 1024
#define HH 16
#define GG 4
#define HD 64
#define KV 256
#define ROWS (BB * TT)  // 4096

// Q scale with folded log2(e) for exp2-based softmax
#define QSCALE (0.125f * 1.44269504088896f)

// Scratch (allocation-free rule: __device__ globals)
__device__ __half g_Xh[ROWS * CC];    // fp16 x
__device__ __half g_Qh[ROWS * CC];    // fp16 Q (pre-scaled by QSCALE)
__device__ __half g_Kh[ROWS * KV];    // fp16 K, row-major
__device__ __half g_Vt[ROWS * KV];    // fp16 V TRANSPOSED: [b][g][d=64][t=2048]
__device__ __half g_Oh[ROWS * CC];    // fp16 attention output
__device__ __half g_Wqt[CC * CC];     // fp16 weights TRANSPOSED [n][k]
__device__ __half g_Wkt[KV * CC];
__device__ __half g_Wvt[KV * CC];
__device__ __half g_Wpt[CC * CC];

// ---------------------------------------------------------------------------
// helpers
// ---------------------------------------------------------------------------
__device__ __forceinline__ uint32_t smem_u32(const void* p) {
    uint32_t a;
    asm("{ .reg .u64 t; cvta.to.shared.u64 t, %1; cvt.u32.u64 %0, t; }"
        : "=r"(a) : "l"(p));
    return a;
}

__device__ __forceinline__ void cp_async16(uint32_t saddr, const void* g) {
    asm volatile("cp.async.cg.shared.global [%0], [%1], 16;"
                 :: "r"(saddr), "l"(g) : "memory");
}
#define CP_COMMIT() asm volatile("cp.async.commit_group;" ::: "memory")
#define CP_WAIT(n)  asm volatile("cp.async.wait_group %0;" :: "n"(n) : "memory")

// fp16 m16n8k16, fp32 accum
__device__ __forceinline__ void mma_f16(float* d, const unsigned* a,
                                        unsigned b0, unsigned b1) {
    asm volatile(
        "mma.sync.aligned.m16n8k16.row.col.f32.f16.f16.f32 "
        "{%0,%1,%2,%3}, {%4,%5,%6,%7}, {%8,%9}, {%0,%1,%2,%3};"
        : "+f"(d[0]), "+f"(d[1]), "+f"(d[2]), "+f"(d[3])
        : "r"(a[0]), "r"(a[1]), "r"(a[2]), "r"(a[3]),
          "r"(b0), "r"(b1));
}

// ldmatrix x4: 4 8x8 b16 tiles, lane r supplies row r%8 of tile r/8
__device__ __forceinline__ void ldsm_x4(unsigned& r0, unsigned& r1,
                                        unsigned& r2, unsigned& r3,
                                        uint32_t addr) {
    asm volatile("ldmatrix.sync.aligned.m8n8.x4.shared.b16 {%0,%1,%2,%3}, [%4];"
                 : "=r"(r0), "=r"(r1), "=r"(r2), "=r"(r3) : "r"(addr));
}

// single-instruction MUFU exp2
__device__ __forceinline__ float ex2(float x) {
    float y;
    asm("ex2.approx.ftz.f32 %0, %1;" : "=f"(y) : "f"(x));
    return y;
}

// pack two floats into one fp16x2 register (FULL 32 bits)
__device__ __forceinline__ unsigned pack_half2(float a, float b) {
    __half2 h = __floats2half2_rn(a, b);
    return *reinterpret_cast<unsigned*>(&h);
}

// ---------------------------------------------------------------------------
// Prepass 1: x -> fp16
// ---------------------------------------------------------------------------
__global__ void __launch_bounds__(256) cvt_x16_kernel(
    const float* __restrict__ in, __half* __restrict__ out, int n4)
{
    int i = blockIdx.x * 256 + threadIdx.x;
    if (i < n4) {
        float4 v = ((const float4*)in)[i];
        __half2 h0 = __floats2half2_rn(v.x, v.y);
        __half2 h1 = __floats2half2_rn(v.z, v.w);
        *(__half2*)&out[i * 4]     = h0;
        *(__half2*)&out[i * 4 + 2] = h1;
    }
}

// Prepass 2: weights -> fp16 TRANSPOSED  out[n*K + k] = in[k*N + n]
// Tiled 32x32 via smem: coalesced read (n contiguous) and write (k contiguous).
__global__ void __launch_bounds__(256) cvt_wT_kernel(
    const float* __restrict__ Wq, __half* __restrict__ Wqt,
    const float* __restrict__ Wk, __half* __restrict__ Wkt,
    const float* __restrict__ Wv, __half* __restrict__ Wvt,
    const float* __restrict__ Wp, __half* __restrict__ Wpt)
{
    const int m = blockIdx.z;
    const float* in; __half* out; int N;
    if (m == 0)      { in = Wq; out = Wqt; N = CC; }
    else if (m == 1) { in = Wk; out = Wkt; N = KV; }
    else if (m == 2) { in = Wv; out = Wvt; N = KV; }
    else             { in = Wp; out = Wpt; N = CC; }
    const int bk = blockIdx.x << 5;
    const int bn = blockIdx.y << 5;
    if (bn >= N) return;

    __shared__ float t[32][33];
    const int tx = threadIdx.x & 31;
    const int ty = threadIdx.x >> 5;
#pragma unroll
    for (int j = ty; j < 32; j += 8)
        t[j][tx] = in[(size_t)(bk + j) * N + bn + tx];
    __syncthreads();
#pragma unroll
    for (int j = ty; j < 32; j += 8)
        out[(size_t)(bn + j) * CC + bk + tx] = __float2half_rn(t[tx][j]);
}

// ---------------------------------------------------------------------------
// FP16 mma.sync GEMM v6: C = A(MxK fp16) @ Wt(NxK fp16)^T + bias
// 128x128 block tile, BK=32, 128 threads (4 warps 2x2), warp tile 64x64.
// ALL fragments via ldmatrix.x4. 2-stage cp.async.
// Smem: A [128 m][40], B [128 n][40] per stage (stride 80B -> conflict-free
// ldmatrix: phases 5r+t, gcd(5,32)=1).
// Epilogue modes: 0 fp32 out; 1 fp16 Q*QSCALE; 2 fp16 K; 3 fp16 V transposed.
// ---------------------------------------------------------------------------
#define G_ST 40
#define G_STAGE (256 * G_ST)                      // A+B halves = 10240
#define GEMM_SMEM_BYTES (2 * G_STAGE * 2)         // 40960

__device__ __forceinline__ void gemm_issue16(
    __half* smem_h, int st, const __half* __restrict__ Ag,
    const __half* __restrict__ Bg, int Kdim, int k0, int tid)
{
    __half* dA = smem_h + st * G_STAGE;
    __half* dB = dA + 128 * G_ST;
#pragma unroll
    for (int t = 0; t < 4; t++) {
        int ch = tid + (t << 7);
        int r = ch >> 2;
        int c8 = (ch & 3) << 3;
        cp_async16(smem_u32(dA + r * G_ST + c8),
                   Ag + (size_t)r * Kdim + k0 + c8);
        cp_async16(smem_u32(dB + r * G_ST + c8),
                   Bg + (size_t)r * Kdim + k0 + c8);
    }
}

__device__ __forceinline__ void gemm_body16(
    const __half* __restrict__ A, const __half* __restrict__ Bt,
    const float* __restrict__ bias, void* __restrict__ Cd,
    int N, int Kdim, int bx, int by, __half* smem_h, int mode)
{
    const int tid = threadIdx.x;
    const int lane = tid & 31;
    const int warp = tid >> 5;
    const int gid = lane >> 2;
    const int tig = lane & 3;
    const int wm = (warp & 1) << 6;
    const int wn = (warp >> 1) << 6;
    const int bm = by << 7;
    const int bn = bx << 7;

    const __half* Ag = A + (size_t)bm * Kdim;
    const __half* Bg = Bt + (size_t)bn * Kdim;
    const int ntiles = Kdim >> 5;

    // ldmatrix lane offsets (halves):
    //   A: msel bit0 -> +8 rows(m), bit1 -> +8 cols(k)
    //   B: msel bit0 -> +8 cols(k), bit1 -> +8 rows(n)
    const int mrow = lane & 7;
    const int msel = lane >> 3;
    const int offA = (((msel & 1) << 3) + mrow) * G_ST + ((msel >> 1) << 3);
    const int offB = (((msel >> 1) << 3) + mrow) * G_ST + ((msel & 1) << 3);
    const uint32_t smem_b = smem_u32(smem_h);

    float acc[4][8][4];
#pragma unroll
    for (int mi = 0; mi < 4; mi++)
#pragma unroll
        for (int ni = 0; ni < 8; ni++)
#pragma unroll
            for (int c = 0; c < 4; c++) acc[mi][ni][c] = 0.0f;

    gemm_issue16(smem_h, 0, Ag, Bg, Kdim, 0, tid);
    CP_COMMIT();

    for (int kt = 0; kt < ntiles; kt++) {
        if (kt + 1 < ntiles) {
            gemm_issue16(smem_h, (kt + 1) & 1, Ag, Bg, Kdim, (kt + 1) << 5, tid);
            CP_COMMIT();
            CP_WAIT(1);
        } else {
            CP_WAIT(0);
        }
        __syncthreads();

        const uint32_t aS = smem_b + (((kt & 1) * G_STAGE) << 1);
        const uint32_t bS = aS + ((128 * G_ST) << 1);
#pragma unroll
        for (int jj = 0; jj < 2; jj++) {
            unsigned a[4][4];
#pragma unroll
            for (int mi = 0; mi < 4; mi++)
                ldsm_x4(a[mi][0], a[mi][1], a[mi][2], a[mi][3],
                        aS + (((wm + (mi << 4)) * G_ST + (jj << 4) + offA) << 1));
#pragma unroll
            for (int nip = 0; nip < 4; nip++) {
                unsigned b0, b1, b2, b3;
                ldsm_x4(b0, b1, b2, b3,
                        bS + (((wn + (nip << 4)) * G_ST + (jj << 4) + offB) << 1));
#pragma unroll
                for (int mi = 0; mi < 4; mi++) {
                    mma_f16(acc[mi][2 * nip],     a[mi], b0, b1);
                    mma_f16(acc[mi][2 * nip + 1], a[mi], b2, b3);
                }
            }
        }
        __syncthreads();
    }

#pragma unroll
    for (int mi = 0; mi < 4; mi++) {
        int r0 = bm + wm + (mi << 4) + gid;
#pragma unroll
        for (int ni = 0; ni < 8; ni++) {
            int c = bn + wn + (ni << 3) + (tig << 1);
            float2 bb = *(const float2*)&bias[c];
            float o00 = acc[mi][ni][0] + bb.x;
            float o01 = acc[mi][ni][1] + bb.y;
            float o10 = acc[mi][ni][2] + bb.x;
            float o11 = acc[mi][ni][3] + bb.y;
            if (mode == 0) {
                float* C = (float*)Cd;
                *(float2*)&C[(size_t)r0 * N + c] = make_float2(o00, o01);
                *(float2*)&C[(size_t)(r0 + 8) * N + c] = make_float2(o10, o11);
            } else if (mode == 1) {
                __half* C = (__half*)Cd;
                *(__half2*)&C[(size_t)r0 * N + c] =
                    __floats2half2_rn(o00 * QSCALE, o01 * QSCALE);
                *(__half2*)&C[(size_t)(r0 + 8) * N + c] =
                    __floats2half2_rn(o10 * QSCALE, o11 * QSCALE);
            } else if (mode == 2) {
                __half* C = (__half*)Cd;
                *(__half2*)&C[(size_t)r0 * N + c] = __floats2half2_rn(o00, o01);
                *(__half2*)&C[(size_t)(r0 + 8) * N + c] = __floats2half2_rn(o10, o11);
            } else {
                // V transposed: Vt[((b*G+g)*64 + d) * TT + t]
                __half* C = (__half*)Cd;
                int gg = c >> 6, d = c & 63;
                int b0_ = r0 >> 11, t0 = r0 & 2047;
                int b1_ = (r0 + 8) >> 11, t1 = (r0 + 8) & 2047;
                size_t base0 = (size_t)(b0_ * GG + gg) * HD;
                size_t base1 = (size_t)(b1_ * GG + gg) * HD;
                C[(base0 + d) * TT + t0]     = __float2half_rn(o00);
                C[(base0 + d + 1) * TT + t0] = __float2half_rn(o01);
                C[(base1 + d) * TT + t1]     = __float2half_rn(o10);
                C[(base1 + d + 1) * TT + t1] = __float2half_rn(o11);
            }
        }
    }
}

__global__ void __launch_bounds__(128, 3) gemm_qkv_kernel(
    const __half* __restrict__ Xh,
    const __half* __restrict__ Wq, const float* __restrict__ bq, __half* __restrict__ Qh,
    const __half* __restrict__ Wk, const float* __restrict__ bk, __half* __restrict__ Kh,
    const __half* __restrict__ Wv, const float* __restrict__ bv, __half* __restrict__ Vt)
{
    extern __shared__ __align__(16) __half smem_h[];
    const int bx = blockIdx.x;
    const __half* Bw; const float* bias; void* Cd; int N, bxx, mode;
    if (bx < 8)       { Bw = Wq; bias = bq; Cd = Qh; N = CC; bxx = bx;      mode = 1; }
    else if (bx < 10) { Bw = Wk; bias = bk; Cd = Kh; N = KV; bxx = bx - 8;  mode = 2; }
    else              { Bw = Wv; bias = bv; Cd = Vt; N = KV; bxx = bx - 10; mode = 3; }
    gemm_body16(Xh, Bw, bias, Cd, N, CC, bxx, blockIdx.y, smem_h, mode);
}

__global__ void __launch_bounds__(128, 3) gemm_p_kernel(
    const __half* __restrict__ A, const __half* __restrict__ Wp,
    const float* __restrict__ bp, float* __restrict__ out)
{
    extern __shared__ __align__(16) __half smem_h[];
    gemm_body16(A, Wp, bp, out, CC, CC, blockIdx.x, blockIdx.y, smem_h, 0);
}

// ---------------------------------------------------------------------------
// Causal GQA flash attention v4 (unchanged from R16): fp16 m16n8k16.
// Block = 128 q-rows x head. 8 warps; k-tile = 64. ldmatrix K/V fragments.
// ---------------------------------------------------------------------------
__global__ void __launch_bounds__(256, 2) attn_f16_kernel(
    const __half* __restrict__ Qh, const __half* __restrict__ Kh,
    const __half* __restrict__ Vt, __half* __restrict__ O)
{
    __shared__ __align__(16) __half sbh[18432];  // 36,864 B

    const int tid = threadIdx.x;
    const int lane = tid & 31;
    const int w = tid >> 5;
    const int gid = lane >> 2;
    const int tig = lane & 3;
    const int qt = gridDim.x - 1 - blockIdx.x;  // heavy tiles first
    const int q0 = qt << 7;
    const int h = blockIdx.y;
    const int b = blockIdx.z;
    const int g = h >> 2;

    const __half* Qg = Qh + (size_t)(b * TT + q0) * CC + h * HD;
    const __half* Kg = Kh + (size_t)(b * TT) * KV + g * HD;
    const __half* Vg = Vt + (size_t)(b * GG + g) * HD * TT;

    // Prologue: stage Q fp16 into [128][72] (overlays K buffers)
#pragma unroll
    for (int t = 0; t < 4; t++) {
        int ch = tid + (t << 8);
        int r = ch >> 3;
        int c8 = (ch & 7) << 3;
        cp_async16(smem_u32(sbh + r * 72 + c8), Qg + (size_t)r * CC + c8);
    }
    CP_COMMIT();
    CP_WAIT(0);
    __syncthreads();

    const int rl = (w << 4) + gid;
    unsigned qa[4][4];
#pragma unroll
    for (int jj = 0; jj < 4; jj++) {
        int base = rl * 72 + (jj << 4) + (tig << 1);
        qa[jj][0] = *(const unsigned*)(sbh + base);
        qa[jj][1] = *(const unsigned*)(sbh + base + 8 * 72);
        qa[jj][2] = *(const unsigned*)(sbh + base + 8);
        qa[jj][3] = *(const unsigned*)(sbh + base + 8 * 72 + 8);
    }
    __syncthreads();  // Q staging dead -> K/V buffers live

    float m_lo = -1e30f, m_hi = -1e30f, l_lo = 0.0f, l_hi = 0.0f;
    float acc[8][4];
#pragma unroll
    for (int nd = 0; nd < 8; nd++)
#pragma unroll
        for (int c = 0; c < 4; c++) acc[nd][c] = 0.0f;

    const int row_lo = q0 + rl;
    const int row_hi = row_lo + 8;
    const int ktiles = (q0 >> 6) + 2;

    const int mrow = lane & 7;
    const int msel = lane >> 3;
    const int laneoff = (((msel >> 1) << 3) + mrow) * 72 + ((msel & 1) << 3);
    const uint32_t sb32 = smem_u32(sbh);

#define ATTN_ISSUE(kt_) do {                                                \
    int _st = (kt_) & 1;                                                    \
    int _k0 = (kt_) << 6;                                                   \
    _Pragma("unroll")                                                       \
    for (int _t = 0; _t < 2; _t++) {                                        \
        int _ch = tid + (_t << 8);                                          \
        int _r = _ch >> 3, _c8 = (_ch & 7) << 3;                            \
        cp_async16(smem_u32(sbh + _st * 4608 + _r * 72 + _c8),              \
                   Kg + (size_t)(_k0 + _r) * KV + _c8);                     \
        cp_async16(smem_u32(sbh + 9216 + _st * 4608 + _r * 72 + _c8),       \
                   Vg + (size_t)_r * TT + _k0 + _c8);                       \
    }                                                                       \
} while (0)

    ATTN_ISSUE(0);
    CP_COMMIT();

    for (int kt = 0; kt < ktiles; kt++) {
        if (kt + 1 < ktiles) {
            ATTN_ISSUE(kt + 1);
            CP_COMMIT();
            CP_WAIT(1);
        } else {
            CP_WAIT(0);
        }
        __syncthreads();

        const int st = kt & 1;
        const uint32_t kbase = sb32 + ((st * 4608 + laneoff) << 1);
        const uint32_t vbase = sb32 + ((9216 + st * 4608 + laneoff) << 1);
        const int k0 = kt << 6;

        // S = Q @ K^T
        float s[8][4];
#pragma unroll
        for (int ni = 0; ni < 8; ni++)
#pragma unroll
            for (int c = 0; c < 4; c++) s[ni][c] = 0.0f;

#pragma unroll
        for (int jj = 0; jj < 4; jj++) {
#pragma unroll
            for (int nip = 0; nip < 4; nip++) {
                unsigned b00, b01, b10, b11;
                ldsm_x4(b00, b01, b10, b11,
                        kbase + ((nip * 1152 + jj * 16) << 1));
                mma_f16(s[2 * nip],     qa[jj], b00, b01);
                mma_f16(s[2 * nip + 1], qa[jj], b10, b11);
            }
        }

        // causal mask
        if (k0 + 63 > q0) {
#pragma unroll
            for (int ni = 0; ni < 8; ni++) {
                int cg = k0 + (ni << 3) + (tig << 1);
                if (cg > row_lo)     s[ni][0] = -1e30f;
                if (cg + 1 > row_lo) s[ni][1] = -1e30f;
                if (cg > row_hi)     s[ni][2] = -1e30f;
                if (cg + 1 > row_hi) s[ni][3] = -1e30f;
            }
        }

        // online softmax
        float mx_lo = -1e30f, mx_hi = -1e30f;
#pragma unroll
        for (int ni = 0; ni < 8; ni++) {
            mx_lo = fmaxf(mx_lo, fmaxf(s[ni][0], s[ni][1]));
            mx_hi = fmaxf(mx_hi, fmaxf(s[ni][2], s[ni][3]));
        }
        mx_lo = fmaxf(mx_lo, __shfl_xor_sync(0xffffffffu, mx_lo, 1));
        mx_lo = fmaxf(mx_lo, __shfl_xor_sync(0xffffffffu, mx_lo, 2));
        mx_hi = fmaxf(mx_hi, __shfl_xor_sync(0xffffffffu, mx_hi, 1));
        mx_hi = fmaxf(mx_hi, __shfl_xor_sync(0xffffffffu, mx_hi, 2));

        float mn_lo = fmaxf(m_lo, mx_lo);
        float mn_hi = fmaxf(m_hi, mx_hi);
        bool rescale = (mn_lo > m_lo) || (mn_hi > m_hi);
        float alpha_lo = ex2(m_lo - mn_lo);
        float alpha_hi = ex2(m_hi - mn_hi);
        m_lo = mn_lo; m_hi = mn_hi;

        float sum_lo = 0.0f, sum_hi = 0.0f;
#pragma unroll
        for (int ni = 0; ni < 8; ni++) {
            s[ni][0] = ex2(s[ni][0] - mn_lo);
            s[ni][1] = ex2(s[ni][1] - mn_lo);
            s[ni][2] = ex2(s[ni][2] - mn_hi);
            s[ni][3] = ex2(s[ni][3] - mn_hi);
            sum_lo += s[ni][0] + s[ni][1];
            sum_hi += s[ni][2] + s[ni][3];
        }
        sum_lo += __shfl_xor_sync(0xffffffffu, sum_lo, 1);
        sum_lo += __shfl_xor_sync(0xffffffffu, sum_lo, 2);
        sum_hi += __shfl_xor_sync(0xffffffffu, sum_hi, 1);
        sum_hi += __shfl_xor_sync(0xffffffffu, sum_hi, 2);
        l_lo = l_lo * alpha_lo + sum_lo;
        l_hi = l_hi * alpha_hi + sum_hi;

        if (rescale) {
#pragma unroll
            for (int nd = 0; nd < 8; nd++) {
                acc[nd][0] *= alpha_lo; acc[nd][1] *= alpha_lo;
                acc[nd][2] *= alpha_hi; acc[nd][3] *= alpha_hi;
            }
        }

        // P: C-fragment of S == A-fragment for PV; pack in registers.
        unsigned pa[4][4];
#pragma unroll
        for (int jj2 = 0; jj2 < 4; jj2++) {
            pa[jj2][0] = pack_half2(s[2*jj2][0],   s[2*jj2][1]);
            pa[jj2][1] = pack_half2(s[2*jj2][2],   s[2*jj2][3]);
            pa[jj2][2] = pack_half2(s[2*jj2+1][0], s[2*jj2+1][1]);
            pa[jj2][3] = pack_half2(s[2*jj2+1][2], s[2*jj2+1][3]);
        }

        // O += P @ V
#pragma unroll
        for (int jj2 = 0; jj2 < 4; jj2++) {
#pragma unroll
            for (int ndp = 0; ndp < 4; ndp++) {
                unsigned v00, v01, v10, v11;
                ldsm_x4(v00, v01, v10, v11,
                        vbase + ((ndp * 1152 + jj2 * 16) << 1));
                mma_f16(acc[2 * ndp],     pa[jj2], v00, v01);
                mma_f16(acc[2 * ndp + 1], pa[jj2], v10, v11);
            }
        }
        __syncthreads();
    }

    // epilogue: normalize, emit fp16 O
    float inv_lo = 1.0f / l_lo;
    float inv_hi = 1.0f / l_hi;
    __half* Og = O + (size_t)(b * TT + q0 + rl) * CC + h * HD;
#pragma unroll
    for (int nd = 0; nd < 8; nd++) {
        int c = (nd << 3) + (tig << 1);
        *(__half2*)&Og[c] =
            __floats2half2_rn(acc[nd][0] * inv_lo, acc[nd][1] * inv_lo);
        *(__half2*)&Og[(size_t)8 * CC + c] =
            __floats2half2_rn(acc[nd][2] * inv_hi, acc[nd][3] * inv_hi);
    }
#undef ATTN_ISSUE
}

// ---------------------------------------------------------------------------
extern "C" void kernel_launch(void* const* d_in, const int* in_sizes, int n_in,
                              void* d_out, int out_size)
{
    (void)in_sizes; (void)n_in; (void)out_size;
    const float* x  = (const float*)d_in[0];
    const float* Wq = (const float*)d_in[1];
    const float* bq = (const float*)d_in[2];
    const float* Wk = (const float*)d_in[3];
    const float* bk = (const float*)d_in[4];
    const float* Wv = (const float*)d_in[5];
    const float* bv = (const float*)d_in[6];
    const float* Wp = (const float*)d_in[7];
    const float* bp = (const float*)d_in[8];
    float* out = (float*)d_out;

    __half *Xh, *Qh, *Kh, *Vtp, *Oh, *Wqt, *Wkt, *Wvt, *Wpt;
    cudaGetSymbolAddress((void**)&Xh, g_Xh);
    cudaGetSymbolAddress((void**)&Qh, g_Qh);
    cudaGetSymbolAddress((void**)&Kh, g_Kh);
    cudaGetSymbolAddress((void**)&Vtp, g_Vt);
    cudaGetSymbolAddress((void**)&Oh, g_Oh);
    cudaGetSymbolAddress((void**)&Wqt, g_Wqt);
    cudaGetSymbolAddress((void**)&Wkt, g_Wkt);
    cudaGetSymbolAddress((void**)&Wvt, g_Wvt);
    cudaGetSymbolAddress((void**)&Wpt, g_Wpt);

    cudaFuncSetAttribute(gemm_qkv_kernel,
                         cudaFuncAttributeMaxDynamicSharedMemorySize, GEMM_SMEM_BYTES);
    cudaFuncSetAttribute(gemm_p_kernel,
                         cudaFuncAttributeMaxDynamicSharedMemorySize, GEMM_SMEM_BYTES);

    // Prepass: x -> fp16; weights -> fp16 transposed [n][k]
    cvt_x16_kernel<<<(ROWS * CC / 4 + 255) / 256, 256>>>(x, Xh, ROWS * CC / 4);
    cvt_wT_kernel<<<dim3(CC / 32, CC / 32, 4), 256>>>(
        Wq, Wqt, Wk, Wkt, Wv, Wvt, Wp, Wpt);

    // Fused Q/K/V projections (ldmatrix operands; V emitted transposed)
    gemm_qkv_kernel<<<dim3(12, ROWS / 128), 128, GEMM_SMEM_BYTES>>>(
        Xh, Wqt, bq, Qh, Wkt, bk, Kh, Wvt, bv, Vtp);

    // Causal GQA attention (unchanged)
    attn_f16_kernel<<<dim3(TT / 128, HH, BB), 256>>>(Qh, Kh, Vtp, Oh);

    // Output projection (ldmatrix operands)
    gemm_p_kernel<<<dim3(CC / 128, ROWS / 128), 128, GEMM_SMEM_BYTES>>>(
        Oh, Wpt, bp, out);
}